// round 10
// baseline (speedup 1.0000x reference)
#include <cuda_runtime.h>
#include <cstdint>

// GCNEncoder: N=100000, E=3200000, 128 -> 16 -> 64
#define NMAX   100000
#define EMAX   3200000
#define IN_C   128
#define HID    16
#define OUTC   64
#define SCHUNK 1024   // scan chunk (256 threads * 4)

// ---------------- scratch (__device__ globals; no allocations allowed) ------
__device__ float g_dinv[NMAX];
__device__ int   g_cnt [NMAX];            // in-degree histogram
__device__ int   g_cur [NMAX];            // fill cursors (init = rowptr)
__device__ int   g_rowptr[NMAX + 1];      // CSR offsets (by destination)
__device__ int   g_bsum[256];             // scan block sums
__device__ int   g_boff[256];             // scanned block offsets
__device__ int   g_csrc[EMAX];            // CSR source indices
__device__ float g_h1s [NMAX * HID];      // (x @ W1) * dinv[row]
__device__ float g_zs  [NMAX * HID];      // relu(out1) * dinv[row]
__device__ int   g_is32;

// ---------------- kernels ----------------------------------------------------

// Sniff index dtype: sample words from BOTH halves of the int64 view.
// If any sampled int64 word is >= N, the data is actually int32 (two packed
// indices per word make huge int64 values with overwhelming probability).
__global__ void detect_kernel(const void* ei, long long words, long long n_nodes) {
    __shared__ int s;
    if (threadIdx.x == 0) s = 0;
    __syncthreads();
    const long long* p = (const long long*)ei;
    long long half = words >> 1;
    long long cnt = half < 512 ? half : 512;
    for (long long i = threadIdx.x; i < cnt; i += blockDim.x) {
        if ((unsigned long long)p[i] >= (unsigned long long)n_nodes) s = 1;
        if ((unsigned long long)p[half + i] >= (unsigned long long)n_nodes) s = 1;
    }
    __syncthreads();
    if (threadIdx.x == 0) g_is32 = s;
}

// In-degree histogram over destinations (col).
__global__ void deg_kernel(const void* ei, long long E) {
    long long e = (long long)blockIdx.x * blockDim.x + threadIdx.x;
    if (e >= E) return;
    int c;
    if (g_is32) c = ((const int*)ei)[E + e];
    else        c = (int)((const long long*)ei)[E + e];
    atomicAdd(&g_cnt[c], 1);
}

// ---- 3-phase exclusive scan of g_cnt -> g_rowptr; dinv fused into phase 1 ---
__global__ __launch_bounds__(256) void scan1_kernel(int n) {
    __shared__ int wsum[8];
    __shared__ int woff[8];
    int t = threadIdx.x;
    int base = blockIdx.x * SCHUNK + t * 4;
    int v0 = base + 0 < n ? g_cnt[base + 0] : 0;
    int v1 = base + 1 < n ? g_cnt[base + 1] : 0;
    int v2 = base + 2 < n ? g_cnt[base + 2] : 0;
    int v3 = base + 3 < n ? g_cnt[base + 3] : 0;
    // fused dinv: rsqrt(deg + 1)  (+1 = self loop)
    if (base + 0 < n) g_dinv[base + 0] = rsqrtf((float)v0 + 1.0f);
    if (base + 1 < n) g_dinv[base + 1] = rsqrtf((float)v1 + 1.0f);
    if (base + 2 < n) g_dinv[base + 2] = rsqrtf((float)v2 + 1.0f);
    if (base + 3 < n) g_dinv[base + 3] = rsqrtf((float)v3 + 1.0f);
    int tsum = v0 + v1 + v2 + v3;
    int lane = t & 31, w = t >> 5;
    int x = tsum;
#pragma unroll
    for (int off = 1; off < 32; off <<= 1) {
        int y = __shfl_up_sync(0xffffffff, x, off);
        if (lane >= off) x += y;
    }
    if (lane == 31) wsum[w] = x;
    __syncthreads();
    if (t == 0) {
        int acc = 0;
#pragma unroll
        for (int i = 0; i < 8; i++) { int tmp = wsum[i]; woff[i] = acc; acc += tmp; }
        g_bsum[blockIdx.x] = acc;
    }
    __syncthreads();
    int excl = woff[w] + (x - tsum);
    if (base + 0 < n) g_rowptr[base + 0] = excl;
    if (base + 1 < n) g_rowptr[base + 1] = excl + v0;
    if (base + 2 < n) g_rowptr[base + 2] = excl + v0 + v1;
    if (base + 3 < n) g_rowptr[base + 3] = excl + v0 + v1 + v2;
}

__global__ void scan2_kernel(int nb) {
    if (threadIdx.x == 0) {
        int acc = 0;
        for (int i = 0; i < nb; i++) { int tmp = g_bsum[i]; g_boff[i] = acc; acc += tmp; }
    }
}

// add block offsets; also initialize fill cursors to segment starts
__global__ void scan3_kernel(long long Nn, long long E) {
    long long i = (long long)blockIdx.x * blockDim.x + threadIdx.x;
    if (i < Nn) {
        int v = g_rowptr[i] + g_boff[i / SCHUNK];
        g_rowptr[i] = v;
        g_cur[i] = v;
    }
    if (i == 0) g_rowptr[Nn] = (int)E;
}

// Fill CSR: cursor-only atomic (g_cur pre-initialized to rowptr).
__global__ void fill_kernel(const void* ei, long long E) {
    long long e = (long long)blockIdx.x * blockDim.x + threadIdx.x;
    if (e >= E) return;
    int r, c;
    if (g_is32) {
        const int* p = (const int*)ei;
        r = p[e]; c = p[E + e];
    } else {
        const long long* p = (const long long*)ei;
        r = (int)p[e]; c = (int)p[E + e];
    }
    int pos = atomicAdd(&g_cur[c], 1);
    g_csrc[pos] = r;
}

// h1s = (x @ W1) * dinv[row]
// 8 lanes per row, 4 rows per warp: fully coalesced x loads.
// W1 in smem with conflict-free swizzle:
//   physical row p(k) = k ^ ((k>>2)&1), quad q4 = (j4 + ((k>>3)&3)) & 3
__global__ __launch_bounds__(256) void mm1_kernel(const float* __restrict__ x,
                                                  const float* __restrict__ W1,
                                                  long long Nn) {
    __shared__ float Ws[IN_C * HID];   // 8 KB, swizzled permutation
    int tid = threadIdx.x;
    for (int i = tid; i < IN_C * HID; i += 256) {
        int k = i >> 4, j = i & 15;
        int j4 = j >> 2, jj = j & 3;
        int prow = k ^ ((k >> 2) & 1);
        int q4 = (j4 + ((k >> 3) & 3)) & 3;
        Ws[prow * 16 + q4 * 4 + jj] = W1[i];
    }
    __syncthreads();

    int warp = tid >> 5, lane = tid & 31;
    int rr = lane >> 3, kk = lane & 7;
    int kk1 = kk & 1, kk2 = kk >> 1;
    long long row = (long long)blockIdx.x * 32 + warp * 4 + rr;
    bool valid = row < Nn;
    long long rsafe = valid ? row : Nn - 1;
    const float4* xr = (const float4*)(x + rsafe * IN_C);

    float acc[16];
#pragma unroll
    for (int j = 0; j < 16; j++) acc[j] = 0.f;

    int rowoff_kk = kk * 64;   // (4*kk)*16 floats
#pragma unroll
    for (int it = 0; it < 4; it++) {
        float4 v = __ldg(&xr[it * 8 + kk]);
        float xs4[4] = {v.x, v.y, v.z, v.w};
        int rowbase = it * 512 + rowoff_kk;   // (32*it + 4*kk)*16
#pragma unroll
        for (int s = 0; s < 4; s++) {
            float xv = xs4[s];
            int prow_off = rowbase + (s ^ kk1) * 16;
#pragma unroll
            for (int j4 = 0; j4 < 4; j4++) {
                int qo = ((j4 + kk2) & 3) * 4;
                float4 wv = *(const float4*)&Ws[prow_off + qo];
                acc[j4 * 4 + 0] += xv * wv.x;
                acc[j4 * 4 + 1] += xv * wv.y;
                acc[j4 * 4 + 2] += xv * wv.z;
                acc[j4 * 4 + 3] += xv * wv.w;
            }
        }
    }

    // split-exchange reduction across the 8 kk-lanes (16 SHFL total)
    float r8[8];
#pragma unroll
    for (int j = 0; j < 8; j++) {
        float send = (kk & 4) ? acc[j] : acc[j + 8];
        float keep = (kk & 4) ? acc[j + 8] : acc[j];
        r8[j] = keep + __shfl_xor_sync(0xffffffff, send, 4);
    }
    float r4[4];
#pragma unroll
    for (int j = 0; j < 4; j++) {
        float send = (kk & 2) ? r8[j] : r8[j + 4];
        float keep = (kk & 2) ? r8[j + 4] : r8[j];
        r4[j] = keep + __shfl_xor_sync(0xffffffff, send, 2);
    }
#pragma unroll
    for (int j = 0; j < 4; j++)
        r4[j] += __shfl_xor_sync(0xffffffff, r4[j], 1);

    // lane kk holds logical quad (kk>>1); even-kk lanes write
    if (valid && kk1 == 0) {
        float d = g_dinv[row];
        int qd = kk2;
        *(float4*)&g_h1s[row * HID + qd * 4] =
            make_float4(d * r4[0], d * r4[1], d * r4[2], d * r4[3]);
    }
}

// Layer-1 CSR gather + fused fin1.  4-lane team per destination node, 4-edge unroll.
__global__ __launch_bounds__(256) void agg1_kernel(const float* __restrict__ b1,
                                                   long long Nn) {
    long long t = (long long)blockIdx.x * blockDim.x + threadIdx.x;
    long long c = t >> 2;
    int q = (int)(t & 3);
    if (c >= Nn) return;
    int e = g_rowptr[c], end = g_rowptr[c + 1];
    const float4* H = (const float4*)g_h1s;
    float4 a0 = make_float4(0.f, 0.f, 0.f, 0.f);
    float4 a1 = make_float4(0.f, 0.f, 0.f, 0.f);
    for (; e + 3 < end; e += 4) {
        int s0 = __ldg(&g_csrc[e]);
        int s1 = __ldg(&g_csrc[e + 1]);
        int s2 = __ldg(&g_csrc[e + 2]);
        int s3 = __ldg(&g_csrc[e + 3]);
        float4 f0 = __ldg(&H[(long long)s0 * 4 + q]);
        float4 f1 = __ldg(&H[(long long)s1 * 4 + q]);
        float4 f2 = __ldg(&H[(long long)s2 * 4 + q]);
        float4 f3 = __ldg(&H[(long long)s3 * 4 + q]);
        a0.x += f0.x + f2.x; a0.y += f0.y + f2.y; a0.z += f0.z + f2.z; a0.w += f0.w + f2.w;
        a1.x += f1.x + f3.x; a1.y += f1.y + f3.y; a1.z += f1.z + f3.z; a1.w += f1.w + f3.w;
    }
    for (; e < end; e++) {
        int s0 = __ldg(&g_csrc[e]);
        float4 f0 = __ldg(&H[(long long)s0 * 4 + q]);
        a0.x += f0.x; a0.y += f0.y; a0.z += f0.z; a0.w += f0.w;
    }
    float d = g_dinv[c];
    float4 self = H[c * 4 + q];
    float4 b = ((const float4*)b1)[q];
    float4 z;
    z.x = fmaxf(d * (a0.x + a1.x + self.x) + b.x, 0.f) * d;
    z.y = fmaxf(d * (a0.y + a1.y + self.y) + b.y, 0.f) * d;
    z.z = fmaxf(d * (a0.z + a1.z + self.z) + b.z, 0.f) * d;
    z.w = fmaxf(d * (a0.w + a1.w + self.w) + b.w, 0.f) * d;
    ((float4*)g_zs)[c * 4 + q] = z;
}

// Layer-2 CSR gather + fused GEMM (W2) + bias.  4-lane team per node.
__global__ __launch_bounds__(256) void agg2mm_kernel(const float* __restrict__ W2,
                                                     const float* __restrict__ b2,
                                                     float* __restrict__ out,
                                                     long long Nn) {
    __shared__ float Ws[HID * OUTC];   // 4 KB
    for (int i = threadIdx.x; i < HID * OUTC; i += 256) Ws[i] = W2[i];
    __syncthreads();

    long long t = (long long)blockIdx.x * blockDim.x + threadIdx.x;
    long long team = t >> 2;
    int q = (int)(t & 3);
    bool valid = team < Nn;
    long long c = valid ? team : (Nn - 1);

    int e = g_rowptr[c], end = g_rowptr[c + 1];
    const float4* Z = (const float4*)g_zs;
    float4 a0 = make_float4(0.f, 0.f, 0.f, 0.f);
    float4 a1 = make_float4(0.f, 0.f, 0.f, 0.f);
    for (; e + 3 < end; e += 4) {
        int s0 = __ldg(&g_csrc[e]);
        int s1 = __ldg(&g_csrc[e + 1]);
        int s2 = __ldg(&g_csrc[e + 2]);
        int s3 = __ldg(&g_csrc[e + 3]);
        float4 f0 = __ldg(&Z[(long long)s0 * 4 + q]);
        float4 f1 = __ldg(&Z[(long long)s1 * 4 + q]);
        float4 f2 = __ldg(&Z[(long long)s2 * 4 + q]);
        float4 f3 = __ldg(&Z[(long long)s3 * 4 + q]);
        a0.x += f0.x + f2.x; a0.y += f0.y + f2.y; a0.z += f0.z + f2.z; a0.w += f0.w + f2.w;
        a1.x += f1.x + f3.x; a1.y += f1.y + f3.y; a1.z += f1.z + f3.z; a1.w += f1.w + f3.w;
    }
    for (; e < end; e++) {
        int s0 = __ldg(&g_csrc[e]);
        float4 f0 = __ldg(&Z[(long long)s0 * 4 + q]);
        a0.x += f0.x; a0.y += f0.y; a0.z += f0.z; a0.w += f0.w;
    }
    float d = g_dinv[c];
    float4 self = Z[c * 4 + q];
    float vq[4];
    vq[0] = d * (a0.x + a1.x + self.x);
    vq[1] = d * (a0.y + a1.y + self.y);
    vq[2] = d * (a0.z + a1.z + self.z);
    vq[3] = d * (a0.w + a1.w + self.w);

    // gather full v[16] across the 4-lane team via shuffles
    int lane = threadIdx.x & 31;
    int tbase = lane & ~3;
    float vv[HID];
#pragma unroll
    for (int k = 0; k < HID; k++)
        vv[k] = __shfl_sync(0xffffffff, vq[k & 3], tbase + (k >> 2));

    // this lane computes output columns [q*16, q*16+16)
    float o[16];
#pragma unroll
    for (int j4 = 0; j4 < 4; j4++) {
        float4 bb = ((const float4*)b2)[q * 4 + j4];
        o[j4*4+0] = bb.x; o[j4*4+1] = bb.y; o[j4*4+2] = bb.z; o[j4*4+3] = bb.w;
    }
#pragma unroll
    for (int k = 0; k < HID; k++) {
        float xv = vv[k];
        const float* w = &Ws[k * OUTC + q * 16];
#pragma unroll
        for (int j = 0; j < 16; j++) o[j] += xv * w[j];
    }
    if (valid) {
        float4* op = (float4*)(out + c * OUTC + q * 16);
#pragma unroll
        for (int j4 = 0; j4 < 4; j4++)
            op[j4] = make_float4(o[j4*4+0], o[j4*4+1], o[j4*4+2], o[j4*4+3]);
    }
}

// ---------------- launch ----------------------------------------------------
extern "C" void kernel_launch(void* const* d_in, const int* in_sizes, int n_in,
                              void* d_out, int out_size) {
    const float* x  = (const float*)d_in[0];
    const void*  ei = d_in[1];
    const float* W1 = (const float*)d_in[2];
    const float* b1 = (const float*)d_in[3];
    const float* W2 = (const float*)d_in[4];
    const float* b2 = (const float*)d_in[5];
    float* out = (float*)d_out;

    long long Nn = in_sizes[0] / IN_C;
    long long E  = (long long)in_sizes[1] / 2;

    int* p_cnt; cudaGetSymbolAddress((void**)&p_cnt, g_cnt);
    cudaMemsetAsync(p_cnt, 0, Nn * sizeof(int));

    const int T = 256;
    unsigned gE = (unsigned)((E + T - 1) / T);
    unsigned gN = (unsigned)((Nn + T - 1) / T);
    unsigned gT = (unsigned)((4 * Nn + T - 1) / T);
    int nb = (int)((Nn + SCHUNK - 1) / SCHUNK);

    detect_kernel<<<1, 256>>>(ei, 2 * E, Nn);
    deg_kernel   <<<gE, T>>>(ei, E);
    scan1_kernel <<<nb, 256>>>((int)Nn);
    scan2_kernel <<<1, 32>>>(nb);
    scan3_kernel <<<gN, T>>>(Nn, E);
    fill_kernel  <<<gE, T>>>(ei, E);

    mm1_kernel   <<<(unsigned)((Nn + 31) / 32), 256>>>(x, W1, Nn);
    agg1_kernel  <<<gT, T>>>(b1, Nn);
    agg2mm_kernel<<<gT, T>>>(W2, b2, out, Nn);
}

// round 11
// speedup vs baseline: 1.0453x; 1.0453x over previous
#include <cuda_runtime.h>
#include <cstdint>

// GCNEncoder: N=100000, E=3200000, 128 -> 16 -> 64
#define NMAX   100000
#define EMAX   3200000
#define IN_C   128
#define HID    16
#define OUTC   64
#define SCHUNK 1024   // scan chunk (256 threads * 4)

// ---------------- scratch (__device__ globals; no allocations allowed) ------
__device__ float g_dinv[NMAX];
__device__ int   g_cnt [NMAX];            // in-degree histogram
__device__ int   g_cur [NMAX];            // fill cursors (init = rowptr)
__device__ int   g_rowptr[NMAX + 1];      // CSR offsets (by destination)
__device__ int   g_bsum[128];             // scan block sums (nb <= 98)
__device__ int   g_csrc[EMAX];            // CSR source indices
__device__ float g_h1s [NMAX * HID];      // (x @ W1) * dinv[row]
__device__ float g_zs  [NMAX * HID];      // relu(out1) * dinv[row]
__device__ int   g_is32;

// ---------------- kernels ----------------------------------------------------

// Sniff index dtype: sample words from BOTH halves of the int64 view.
__global__ void detect_kernel(const void* ei, long long words, long long n_nodes) {
    __shared__ int s;
    if (threadIdx.x == 0) s = 0;
    __syncthreads();
    const long long* p = (const long long*)ei;
    long long half = words >> 1;
    long long cnt = half < 512 ? half : 512;
    for (long long i = threadIdx.x; i < cnt; i += blockDim.x) {
        if ((unsigned long long)p[i] >= (unsigned long long)n_nodes) s = 1;
        if ((unsigned long long)p[half + i] >= (unsigned long long)n_nodes) s = 1;
    }
    __syncthreads();
    if (threadIdx.x == 0) g_is32 = s;
}

// In-degree histogram over destinations (col).
__global__ void deg_kernel(const void* ei, long long E) {
    long long e = (long long)blockIdx.x * blockDim.x + threadIdx.x;
    if (e >= E) return;
    int c;
    if (g_is32) c = ((const int*)ei)[E + e];
    else        c = (int)((const long long*)ei)[E + e];
    atomicAdd(&g_cnt[c], 1);
}

// ---- scan phase 1: per-chunk exclusive scan of g_cnt; dinv fused ------------
__global__ __launch_bounds__(256) void scan1_kernel(int n) {
    __shared__ int wsum[8];
    __shared__ int woff[8];
    int t = threadIdx.x;
    int base = blockIdx.x * SCHUNK + t * 4;
    int v0 = base + 0 < n ? g_cnt[base + 0] : 0;
    int v1 = base + 1 < n ? g_cnt[base + 1] : 0;
    int v2 = base + 2 < n ? g_cnt[base + 2] : 0;
    int v3 = base + 3 < n ? g_cnt[base + 3] : 0;
    // fused dinv: rsqrt(deg + 1)  (+1 = self loop)
    if (base + 0 < n) g_dinv[base + 0] = rsqrtf((float)v0 + 1.0f);
    if (base + 1 < n) g_dinv[base + 1] = rsqrtf((float)v1 + 1.0f);
    if (base + 2 < n) g_dinv[base + 2] = rsqrtf((float)v2 + 1.0f);
    if (base + 3 < n) g_dinv[base + 3] = rsqrtf((float)v3 + 1.0f);
    int tsum = v0 + v1 + v2 + v3;
    int lane = t & 31, w = t >> 5;
    int x = tsum;
#pragma unroll
    for (int off = 1; off < 32; off <<= 1) {
        int y = __shfl_up_sync(0xffffffff, x, off);
        if (lane >= off) x += y;
    }
    if (lane == 31) wsum[w] = x;
    __syncthreads();
    if (t == 0) {
        int acc = 0;
#pragma unroll
        for (int i = 0; i < 8; i++) { int tmp = wsum[i]; woff[i] = acc; acc += tmp; }
        g_bsum[blockIdx.x] = acc;
    }
    __syncthreads();
    int excl = woff[w] + (x - tsum);
    if (base + 0 < n) g_rowptr[base + 0] = excl;
    if (base + 1 < n) g_rowptr[base + 1] = excl + v0;
    if (base + 2 < n) g_rowptr[base + 2] = excl + v0 + v1;
    if (base + 3 < n) g_rowptr[base + 3] = excl + v0 + v1 + v2;
}

// scan phase 2+3 fused: every block re-scans the (<=128) chunk sums in shared,
// adds the offset, and initializes the fill cursors.
__global__ __launch_bounds__(256) void scan3_kernel(long long Nn, long long E, int nb) {
    __shared__ int sb[128];
    int t = threadIdx.x;
    if (t < 128) sb[t] = (t < nb) ? g_bsum[t] : 0;
    __syncthreads();
#pragma unroll
    for (int off = 1; off < 128; off <<= 1) {
        int v = 0;
        if (t < 128 && t >= off) v = sb[t - off];
        __syncthreads();
        if (t < 128) sb[t] += v;
        __syncthreads();
    }
    long long i = (long long)blockIdx.x * blockDim.x + t;
    if (i < Nn) {
        int chunk = (int)(i / SCHUNK);
        int boff = chunk ? sb[chunk - 1] : 0;
        int v = g_rowptr[i] + boff;
        g_rowptr[i] = v;
        g_cur[i] = v;
    }
    if (i == 0) g_rowptr[Nn] = (int)E;
}

// Fill CSR: cursor-only atomic (g_cur pre-initialized to rowptr).
__global__ void fill_kernel(const void* ei, long long E) {
    long long e = (long long)blockIdx.x * blockDim.x + threadIdx.x;
    if (e >= E) return;
    int r, c;
    if (g_is32) {
        const int* p = (const int*)ei;
        r = p[e]; c = p[E + e];
    } else {
        const long long* p = (const long long*)ei;
        r = (int)p[e]; c = (int)p[E + e];
    }
    int pos = atomicAdd(&g_cur[c], 1);
    g_csrc[pos] = r;
}

// h1s = (x @ W1) * dinv[row]   (measured-fastest variant: per-thread row)
__global__ __launch_bounds__(128) void mm1_kernel(const float* __restrict__ x,
                                                  const float* __restrict__ W1,
                                                  long long Nn) {
    __shared__ float Ws[IN_C * HID];
    for (int i = threadIdx.x; i < IN_C * HID; i += 128) Ws[i] = W1[i];
    __syncthreads();
    long long r = (long long)blockIdx.x * blockDim.x + threadIdx.x;
    if (r >= Nn) return;
    float acc[HID];
#pragma unroll
    for (int j = 0; j < HID; j++) acc[j] = 0.f;
    const float4* xr = (const float4*)(x + r * IN_C);
#pragma unroll 4
    for (int k = 0; k < IN_C / 4; k++) {
        float4 v = __ldg(&xr[k]);
        const float* w = &Ws[(k * 4) * HID];
#pragma unroll
        for (int j = 0; j < HID; j++)
            acc[j] += v.x * w[j] + v.y * w[HID + j] + v.z * w[2 * HID + j] + v.w * w[3 * HID + j];
    }
    float d = g_dinv[r];
    float4* o = (float4*)&g_h1s[r * HID];
#pragma unroll
    for (int q = 0; q < HID / 4; q++)
        o[q] = make_float4(acc[4*q] * d, acc[4*q+1] * d, acc[4*q+2] * d, acc[4*q+3] * d);
}

// Layer-1 aggregation: ONE WARP PER NODE (no divergence across nodes).
// lane = 4*sub + q: sub indexes edges (stride 8), q indexes the float4 quad.
// zs[c] = relu(dinv[c]*(sum_src h1s[src] + h1s[c]) + b1) * dinv[c]
__global__ __launch_bounds__(256) void agg1_kernel(const float* __restrict__ b1,
                                                   long long Nn) {
    long long c = ((long long)blockIdx.x * blockDim.x + threadIdx.x) >> 5;
    if (c >= Nn) return;
    int lane = threadIdx.x & 31;
    int q = lane & 3, sub = lane >> 2;
    int beg = g_rowptr[c], end = g_rowptr[c + 1];
    const float4* H = (const float4*)g_h1s;
    float4 a = make_float4(0.f, 0.f, 0.f, 0.f);
    int e = beg + sub;
    for (; e + 8 < end; e += 16) {
        int s0 = __ldg(&g_csrc[e]);
        int s1 = __ldg(&g_csrc[e + 8]);
        float4 f0 = __ldg(&H[(long long)s0 * 4 + q]);
        float4 f1 = __ldg(&H[(long long)s1 * 4 + q]);
        a.x += f0.x + f1.x; a.y += f0.y + f1.y;
        a.z += f0.z + f1.z; a.w += f0.w + f1.w;
    }
    if (e < end) {
        int s0 = __ldg(&g_csrc[e]);
        float4 f0 = __ldg(&H[(long long)s0 * 4 + q]);
        a.x += f0.x; a.y += f0.y; a.z += f0.z; a.w += f0.w;
    }
    // butterfly over sub (lane bits 2..4): every lane gets the q-total
#pragma unroll
    for (int off = 16; off >= 4; off >>= 1) {
        a.x += __shfl_xor_sync(0xffffffff, a.x, off);
        a.y += __shfl_xor_sync(0xffffffff, a.y, off);
        a.z += __shfl_xor_sync(0xffffffff, a.z, off);
        a.w += __shfl_xor_sync(0xffffffff, a.w, off);
    }
    if (sub == 0) {
        float d = g_dinv[c];
        float4 self = __ldg(&H[c * 4 + q]);
        float4 b = ((const float4*)b1)[q];
        float4 z;
        z.x = fmaxf(d * (a.x + self.x) + b.x, 0.f) * d;
        z.y = fmaxf(d * (a.y + self.y) + b.y, 0.f) * d;
        z.z = fmaxf(d * (a.z + self.z) + b.z, 0.f) * d;
        z.w = fmaxf(d * (a.w + self.w) + b.w, 0.f) * d;
        ((float4*)g_zs)[c * 4 + q] = z;
    }
}

// Layer-2 aggregation + fused GEMM (W2) + bias: ONE WARP PER NODE.
// out[c] = (dinv[c]*(sum_src zs[src] + zs[c])) @ W2 + b2
// Epilogue: each lane computes 2 output columns; coalesced float2 store.
__global__ __launch_bounds__(256) void agg2mm_kernel(const float* __restrict__ W2,
                                                     const float* __restrict__ b2,
                                                     float* __restrict__ out,
                                                     long long Nn) {
    __shared__ float Ws[HID * OUTC];   // 4 KB
    for (int i = threadIdx.x; i < HID * OUTC; i += 256) Ws[i] = W2[i];
    __syncthreads();

    long long c = ((long long)blockIdx.x * blockDim.x + threadIdx.x) >> 5;
    if (c >= Nn) return;
    int lane = threadIdx.x & 31;
    int q = lane & 3;
    int beg = g_rowptr[c], end = g_rowptr[c + 1];
    const float4* Z = (const float4*)g_zs;
    float4 a = make_float4(0.f, 0.f, 0.f, 0.f);
    int e = beg + (lane >> 2);
    for (; e + 8 < end; e += 16) {
        int s0 = __ldg(&g_csrc[e]);
        int s1 = __ldg(&g_csrc[e + 8]);
        float4 f0 = __ldg(&Z[(long long)s0 * 4 + q]);
        float4 f1 = __ldg(&Z[(long long)s1 * 4 + q]);
        a.x += f0.x + f1.x; a.y += f0.y + f1.y;
        a.z += f0.z + f1.z; a.w += f0.w + f1.w;
    }
    if (e < end) {
        int s0 = __ldg(&g_csrc[e]);
        float4 f0 = __ldg(&Z[(long long)s0 * 4 + q]);
        a.x += f0.x; a.y += f0.y; a.z += f0.z; a.w += f0.w;
    }
#pragma unroll
    for (int off = 16; off >= 4; off >>= 1) {
        a.x += __shfl_xor_sync(0xffffffff, a.x, off);
        a.y += __shfl_xor_sync(0xffffffff, a.y, off);
        a.z += __shfl_xor_sync(0xffffffff, a.z, off);
        a.w += __shfl_xor_sync(0xffffffff, a.w, off);
    }
    // every lane now holds the total for its q; fold in self + dinv
    float d = g_dinv[c];
    float4 self = __ldg(&Z[c * 4 + q]);
    float vq[4];
    vq[0] = d * (a.x + self.x);
    vq[1] = d * (a.y + self.y);
    vq[2] = d * (a.z + self.z);
    vq[3] = d * (a.w + self.w);

    // broadcast v[16]: component k lives in vq[k&3] of any lane with lane&3 == k>>2
    float vv[HID];
#pragma unroll
    for (int k = 0; k < HID; k++)
        vv[k] = __shfl_sync(0xffffffff, vq[k & 3], k >> 2);

    // lane computes output columns 2*lane, 2*lane+1
    float2 o = ((const float2*)b2)[lane];
#pragma unroll
    for (int k = 0; k < HID; k++) {
        float xv = vv[k];
        float2 w = ((const float2*)Ws)[k * (OUTC / 2) + lane];
        o.x += xv * w.x;
        o.y += xv * w.y;
    }
    ((float2*)(out + c * OUTC))[lane] = o;
}

// ---------------- launch ----------------------------------------------------
extern "C" void kernel_launch(void* const* d_in, const int* in_sizes, int n_in,
                              void* d_out, int out_size) {
    const float* x  = (const float*)d_in[0];
    const void*  ei = d_in[1];
    const float* W1 = (const float*)d_in[2];
    const float* b1 = (const float*)d_in[3];
    const float* W2 = (const float*)d_in[4];
    const float* b2 = (const float*)d_in[5];
    float* out = (float*)d_out;

    long long Nn = in_sizes[0] / IN_C;
    long long E  = (long long)in_sizes[1] / 2;

    int* p_cnt; cudaGetSymbolAddress((void**)&p_cnt, g_cnt);
    cudaMemsetAsync(p_cnt, 0, Nn * sizeof(int));

    const int T = 256;
    unsigned gE = (unsigned)((E + T - 1) / T);
    unsigned gN = (unsigned)((Nn + T - 1) / T);
    unsigned gW = (unsigned)((Nn * 32 + T - 1) / T);   // warp-per-node kernels
    int nb = (int)((Nn + SCHUNK - 1) / SCHUNK);

    detect_kernel<<<1, 256>>>(ei, 2 * E, Nn);
    deg_kernel   <<<gE, T>>>(ei, E);
    scan1_kernel <<<nb, 256>>>((int)Nn);
    scan3_kernel <<<gN, T>>>(Nn, E, nb);
    fill_kernel  <<<gE, T>>>(ei, E);

    mm1_kernel   <<<(unsigned)((Nn + 127) / 128), 128>>>(x, W1, Nn);
    agg1_kernel  <<<gW, T>>>(b1, Nn);
    agg2mm_kernel<<<gW, T>>>(W2, b2, out, Nn);
}

// round 12
// speedup vs baseline: 1.1073x; 1.0593x over previous
#include <cuda_runtime.h>
#include <cstdint>

// GCNEncoder: N=100000, E=3200000, 128 -> 16 -> 64
#define NMAX   100000
#define EMAX   3200000
#define IN_C   128
#define HID    16
#define OUTC   64
#define SCHUNK 1024   // scan chunk (256 threads * 4)

// ---------------- scratch (__device__ globals; no allocations allowed) ------
__device__ float g_dinv[NMAX];
__device__ int   g_cnt [NMAX];            // in-degree histogram
__device__ int   g_cur [NMAX];            // fill cursors (init = rowptr)
__device__ int   g_rowptr[NMAX + 1];      // CSR offsets (by destination)
__device__ int   g_aggval[128];           // decoupled-lookback chunk aggregates
__device__ int   g_flag  [128];           // 0 = not published, 1 = aggregate ready
__device__ int   g_csrc[EMAX];            // CSR source indices
__device__ float g_h1 [NMAX * HID];       // x @ W1, then scaled by dinv in M2
__device__ float g_zs [NMAX * HID];       // relu(out1) * dinv[row]
__device__ int   g_is32;

// ---------------- setup: zero histogram + flags, sniff index dtype ----------
__global__ __launch_bounds__(256) void setup_kernel(const void* ei, long long E,
                                                    long long Nn, unsigned zBlocks) {
    unsigned bid = blockIdx.x;
    int t = threadIdx.x;
    if (bid < zBlocks) {
        long long i = (long long)bid * 256 + t;
        if (i < Nn) g_cnt[i] = 0;
        if (bid == 0 && t < 128) g_flag[t] = 0;
    } else {
        // dtype sniffer: sample int64 words from both halves of the edge array
        __shared__ int s;
        if (t == 0) s = 0;
        __syncthreads();
        const long long* p = (const long long*)ei;
        long long half = E;               // 2E words total -> halves of E words
        long long cnt = half < 512 ? half : 512;
        for (long long i = t; i < cnt; i += 256) {
            if ((unsigned long long)p[i] >= (unsigned long long)Nn) s = 1;
            if ((unsigned long long)p[half + i] >= (unsigned long long)Nn) s = 1;
        }
        __syncthreads();
        if (t == 0) g_is32 = s;
    }
}

// ---------------- M1: mm1 (unscaled)  ∥  deg histogram ----------------------
// blocks [0, mmBlocks) run the GEMM; the rest run the degree histogram.
__global__ __launch_bounds__(256) void m1_kernel(const float* __restrict__ x,
                                                 const float* __restrict__ W1,
                                                 const void* ei,
                                                 long long Nn, long long E,
                                                 unsigned mmBlocks) {
    __shared__ float Ws[IN_C * HID];   // 8 KB (unused by deg blocks)
    unsigned bid = blockIdx.x;
    int tid = threadIdx.x;
    if (bid < mmBlocks) {
        for (int i = tid; i < IN_C * HID; i += 256) Ws[i] = W1[i];
        __syncthreads();
        long long r = (long long)bid * 256 + tid;
        if (r >= Nn) return;
        float acc[HID];
#pragma unroll
        for (int j = 0; j < HID; j++) acc[j] = 0.f;
        const float4* xr = (const float4*)(x + r * IN_C);
#pragma unroll 4
        for (int k = 0; k < IN_C / 4; k++) {
            float4 v = __ldg(&xr[k]);
            const float* w = &Ws[(k * 4) * HID];
#pragma unroll
            for (int j = 0; j < HID; j++)
                acc[j] += v.x * w[j] + v.y * w[HID + j] + v.z * w[2 * HID + j] + v.w * w[3 * HID + j];
        }
        float4* o = (float4*)&g_h1[r * HID];
#pragma unroll
        for (int q = 0; q < HID / 4; q++)
            o[q] = make_float4(acc[4*q], acc[4*q+1], acc[4*q+2], acc[4*q+3]);
    } else {
        long long e = (long long)(bid - mmBlocks) * 256 + tid;
        if (e >= E) return;
        int c;
        if (g_is32) c = ((const int*)ei)[E + e];
        else        c = (int)((const long long*)ei)[E + e];
        atomicAdd(&g_cnt[c], 1);
    }
}

// ---------------- single-kernel scan (decoupled lookback) --------------------
// 98 blocks, all resident -> spin-safe. Produces final rowptr, cursors, dinv.
__global__ __launch_bounds__(256) void scan_dl_kernel(int n, long long E) {
    __shared__ int wsum[8];
    __shared__ int woff[8];
    __shared__ int s_off;
    int t = threadIdx.x;
    int b = blockIdx.x;
    int base = b * SCHUNK + t * 4;
    int v0 = base + 0 < n ? g_cnt[base + 0] : 0;
    int v1 = base + 1 < n ? g_cnt[base + 1] : 0;
    int v2 = base + 2 < n ? g_cnt[base + 2] : 0;
    int v3 = base + 3 < n ? g_cnt[base + 3] : 0;
    // fused dinv: rsqrt(deg + 1)   (+1 = self loop)
    if (base + 0 < n) g_dinv[base + 0] = rsqrtf((float)v0 + 1.0f);
    if (base + 1 < n) g_dinv[base + 1] = rsqrtf((float)v1 + 1.0f);
    if (base + 2 < n) g_dinv[base + 2] = rsqrtf((float)v2 + 1.0f);
    if (base + 3 < n) g_dinv[base + 3] = rsqrtf((float)v3 + 1.0f);
    int tsum = v0 + v1 + v2 + v3;
    int lane = t & 31, w = t >> 5;
    int x = tsum;
#pragma unroll
    for (int off = 1; off < 32; off <<= 1) {
        int y = __shfl_up_sync(0xffffffff, x, off);
        if (lane >= off) x += y;
    }
    if (lane == 31) wsum[w] = x;
    __syncthreads();
    if (t == 0) {
        int acc = 0;
#pragma unroll
        for (int i = 0; i < 8; i++) { int tmp = wsum[i]; woff[i] = acc; acc += tmp; }
        // publish this chunk's aggregate ASAP
        g_aggval[b] = acc;
        __threadfence();
        ((volatile int*)g_flag)[b] = 1;
    }
    // warp 0: sum all predecessor aggregates (windows of 32)
    if (t < 32) {
        int sum = 0;
        for (int w0 = 0; w0 < b; w0 += 32) {
            int idx = w0 + lane;
            int a = 0;
            if (idx < b) {
                while (((volatile int*)g_flag)[idx] == 0) {}
                __threadfence();
                a = ((volatile int*)g_aggval)[idx];
            }
#pragma unroll
            for (int off = 16; off >= 1; off >>= 1)
                a += __shfl_xor_sync(0xffffffff, a, off);
            sum += a;
        }
        if (lane == 0) s_off = sum;
    }
    __syncthreads();
    int excl = s_off + woff[w] + (x - tsum);
    if (base + 0 < n) { g_rowptr[base + 0] = excl;               g_cur[base + 0] = excl; }
    if (base + 1 < n) { g_rowptr[base + 1] = excl + v0;          g_cur[base + 1] = excl + v0; }
    if (base + 2 < n) { g_rowptr[base + 2] = excl + v0 + v1;     g_cur[base + 2] = excl + v0 + v1; }
    if (base + 3 < n) { g_rowptr[base + 3] = excl + v0 + v1 + v2; g_cur[base + 3] = excl + v0 + v1 + v2; }
    if (base == 0) g_rowptr[n] = (int)E;
}

// ---------------- M2: scale h1 by dinv  ∥  CSR fill --------------------------
__global__ __launch_bounds__(256) void m2_kernel(const void* ei, long long E,
                                                 long long Nn, unsigned scaleBlocks) {
    unsigned bid = blockIdx.x;
    int tid = threadIdx.x;
    if (bid < scaleBlocks) {
        long long i = (long long)bid * 256 + tid;       // float4 index
        if (i < Nn * (HID / 4)) {
            float d = g_dinv[i >> 2];
            float4 v = ((const float4*)g_h1)[i];
            ((float4*)g_h1)[i] = make_float4(v.x * d, v.y * d, v.z * d, v.w * d);
        }
    } else {
        long long e = (long long)(bid - scaleBlocks) * 256 + tid;
        if (e >= E) return;
        int r, c;
        if (g_is32) {
            const int* p = (const int*)ei;
            r = p[e]; c = p[E + e];
        } else {
            const long long* p = (const long long*)ei;
            r = (int)p[e]; c = (int)p[E + e];
        }
        int pos = atomicAdd(&g_cur[c], 1);
        g_csrc[pos] = r;
    }
}

// ---------------- layer-1 aggregation: one warp per node ---------------------
// zs[c] = relu(dinv[c]*(sum_src h1s[src] + h1s[c]) + b1) * dinv[c]
__global__ __launch_bounds__(256) void agg1_kernel(const float* __restrict__ b1,
                                                   long long Nn) {
    long long c = ((long long)blockIdx.x * blockDim.x + threadIdx.x) >> 5;
    if (c >= Nn) return;
    int lane = threadIdx.x & 31;
    int q = lane & 3, sub = lane >> 2;
    int beg = g_rowptr[c], end = g_rowptr[c + 1];
    const float4* H = (const float4*)g_h1;
    float4 a = make_float4(0.f, 0.f, 0.f, 0.f);
    int e = beg + sub;
    for (; e + 8 < end; e += 16) {
        int s0 = __ldg(&g_csrc[e]);
        int s1 = __ldg(&g_csrc[e + 8]);
        float4 f0 = __ldg(&H[(long long)s0 * 4 + q]);
        float4 f1 = __ldg(&H[(long long)s1 * 4 + q]);
        a.x += f0.x + f1.x; a.y += f0.y + f1.y;
        a.z += f0.z + f1.z; a.w += f0.w + f1.w;
    }
    if (e < end) {
        int s0 = __ldg(&g_csrc[e]);
        float4 f0 = __ldg(&H[(long long)s0 * 4 + q]);
        a.x += f0.x; a.y += f0.y; a.z += f0.z; a.w += f0.w;
    }
#pragma unroll
    for (int off = 16; off >= 4; off >>= 1) {
        a.x += __shfl_xor_sync(0xffffffff, a.x, off);
        a.y += __shfl_xor_sync(0xffffffff, a.y, off);
        a.z += __shfl_xor_sync(0xffffffff, a.z, off);
        a.w += __shfl_xor_sync(0xffffffff, a.w, off);
    }
    if (sub == 0) {
        float d = g_dinv[c];
        float4 self = __ldg(&H[c * 4 + q]);
        float4 b = ((const float4*)b1)[q];
        float4 z;
        z.x = fmaxf(d * (a.x + self.x) + b.x, 0.f) * d;
        z.y = fmaxf(d * (a.y + self.y) + b.y, 0.f) * d;
        z.z = fmaxf(d * (a.z + self.z) + b.z, 0.f) * d;
        z.w = fmaxf(d * (a.w + self.w) + b.w, 0.f) * d;
        ((float4*)g_zs)[c * 4 + q] = z;
    }
}

// ---------------- layer-2 aggregation + fused GEMM + bias --------------------
// out[c] = (dinv[c]*(sum_src zs[src] + zs[c])) @ W2 + b2   (one warp per node)
__global__ __launch_bounds__(256) void agg2mm_kernel(const float* __restrict__ W2,
                                                     const float* __restrict__ b2,
                                                     float* __restrict__ out,
                                                     long long Nn) {
    __shared__ float Ws[HID * OUTC];   // 4 KB
    for (int i = threadIdx.x; i < HID * OUTC; i += 256) Ws[i] = W2[i];
    __syncthreads();

    long long c = ((long long)blockIdx.x * blockDim.x + threadIdx.x) >> 5;
    if (c >= Nn) return;
    int lane = threadIdx.x & 31;
    int q = lane & 3;
    int beg = g_rowptr[c], end = g_rowptr[c + 1];
    const float4* Z = (const float4*)g_zs;
    float4 a = make_float4(0.f, 0.f, 0.f, 0.f);
    int e = beg + (lane >> 2);
    for (; e + 8 < end; e += 16) {
        int s0 = __ldg(&g_csrc[e]);
        int s1 = __ldg(&g_csrc[e + 8]);
        float4 f0 = __ldg(&Z[(long long)s0 * 4 + q]);
        float4 f1 = __ldg(&Z[(long long)s1 * 4 + q]);
        a.x += f0.x + f1.x; a.y += f0.y + f1.y;
        a.z += f0.z + f1.z; a.w += f0.w + f1.w;
    }
    if (e < end) {
        int s0 = __ldg(&g_csrc[e]);
        float4 f0 = __ldg(&Z[(long long)s0 * 4 + q]);
        a.x += f0.x; a.y += f0.y; a.z += f0.z; a.w += f0.w;
    }
#pragma unroll
    for (int off = 16; off >= 4; off >>= 1) {
        a.x += __shfl_xor_sync(0xffffffff, a.x, off);
        a.y += __shfl_xor_sync(0xffffffff, a.y, off);
        a.z += __shfl_xor_sync(0xffffffff, a.z, off);
        a.w += __shfl_xor_sync(0xffffffff, a.w, off);
    }
    float d = g_dinv[c];
    float4 self = __ldg(&Z[c * 4 + q]);
    float vq[4];
    vq[0] = d * (a.x + self.x);
    vq[1] = d * (a.y + self.y);
    vq[2] = d * (a.z + self.z);
    vq[3] = d * (a.w + self.w);

    float vv[HID];
#pragma unroll
    for (int k = 0; k < HID; k++)
        vv[k] = __shfl_sync(0xffffffff, vq[k & 3], k >> 2);

    float2 o = ((const float2*)b2)[lane];
#pragma unroll
    for (int k = 0; k < HID; k++) {
        float xv = vv[k];
        float2 w = ((const float2*)Ws)[k * (OUTC / 2) + lane];
        o.x += xv * w.x;
        o.y += xv * w.y;
    }
    ((float2*)(out + c * OUTC))[lane] = o;
}

// ---------------- launch ----------------------------------------------------
extern "C" void kernel_launch(void* const* d_in, const int* in_sizes, int n_in,
                              void* d_out, int out_size) {
    const float* x  = (const float*)d_in[0];
    const void*  ei = d_in[1];
    const float* W1 = (const float*)d_in[2];
    const float* b1 = (const float*)d_in[3];
    const float* W2 = (const float*)d_in[4];
    const float* b2 = (const float*)d_in[5];
    float* out = (float*)d_out;

    long long Nn = in_sizes[0] / IN_C;
    long long E  = (long long)in_sizes[1] / 2;

    const int T = 256;
    unsigned zBlocks  = (unsigned)((Nn + T - 1) / T);            // 391
    unsigned mmBlocks = (unsigned)((Nn + T - 1) / T);            // 391
    unsigned edBlocks = (unsigned)((E + T - 1) / T);             // 12500
    unsigned scBlocks = (unsigned)((Nn * (HID/4) + T - 1) / T);  // 1563
    unsigned gW = (unsigned)((Nn * 32 + T - 1) / T);             // warp-per-node
    int nb = (int)((Nn + SCHUNK - 1) / SCHUNK);                  // 98

    setup_kernel  <<<zBlocks + 1, T>>>(ei, E, Nn, zBlocks);
    m1_kernel     <<<mmBlocks + edBlocks, T>>>(x, W1, ei, Nn, E, mmBlocks);
    scan_dl_kernel<<<nb, T>>>((int)Nn, E);
    m2_kernel     <<<scBlocks + edBlocks, T>>>(ei, E, Nn, scBlocks);   // 4th: profiled
    agg1_kernel   <<<gW, T>>>(b1, Nn);
    agg2mm_kernel <<<gW, T>>>(W2, b2, out, Nn);
}

// round 14
// speedup vs baseline: 1.1718x; 1.0582x over previous
#include <cuda_runtime.h>
#include <cuda_fp16.h>
#include <cstdint>

// GCNEncoder: N=100000, E=3200000, 128 -> 16 -> 64
#define NMAX   100000
#define EMAX   3200000
#define IN_C   128
#define HID    16
#define OUTC   64
#define SCHUNK 1024   // scan chunk (256 threads * 4)

// ---------------- scratch (__device__ globals; no allocations allowed) ------
__device__ float   g_dinv[NMAX];
__device__ int     g_cnt [NMAX];          // in-degree histogram
__device__ int     g_rowptr[NMAX + 1];    // CSR offsets (by destination)
__device__ int     g_aggval[128];         // decoupled-lookback chunk aggregates
__device__ int     g_flag  [128];         // 0 = not published, 1 = ready
__device__ int     g_rank[EMAX];          // per-edge rank within its dest segment
__device__ int     g_csrc[EMAX];          // CSR source indices
__device__ float   g_h1 [NMAX * HID];     // x @ W1 (fp32, unscaled)
__device__ __half2 g_h1h[NMAX * (HID/2)]; // (x @ W1) * dinv  (fp16 gather table)
__device__ __half2 g_zsh[NMAX * (HID/2)]; // relu(...) * dinv (fp16 gather table)
__device__ int     g_is32;

// ---------------- setup: zero histogram + flags, sniff index dtype ----------
__global__ __launch_bounds__(256) void setup_kernel(const void* ei, long long E,
                                                    long long Nn, unsigned zBlocks) {
    unsigned bid = blockIdx.x;
    int t = threadIdx.x;
    if (bid < zBlocks) {
        long long i = (long long)bid * 256 + t;
        if (i < Nn) g_cnt[i] = 0;
        if (bid == 0 && t < 128) g_flag[t] = 0;
    } else {
        __shared__ int s;
        if (t == 0) s = 0;
        __syncthreads();
        const long long* p = (const long long*)ei;
        long long half = E;
        long long cnt = half < 512 ? half : 512;
        for (long long i = t; i < cnt; i += 256) {
            if ((unsigned long long)p[i] >= (unsigned long long)Nn) s = 1;
            if ((unsigned long long)p[half + i] >= (unsigned long long)Nn) s = 1;
        }
        __syncthreads();
        if (t == 0) g_is32 = s;
    }
}

// ---------------- M1: mm1 (unscaled, fp32)  ∥  deg histogram + rank ----------
__global__ __launch_bounds__(256) void m1_kernel(const float* __restrict__ x,
                                                 const float* __restrict__ W1,
                                                 const void* ei,
                                                 long long Nn, long long E,
                                                 unsigned mmBlocks) {
    __shared__ float Ws[IN_C * HID];   // 8 KB (unused by deg blocks)
    unsigned bid = blockIdx.x;
    int tid = threadIdx.x;
    if (bid < mmBlocks) {
        for (int i = tid; i < IN_C * HID; i += 256) Ws[i] = W1[i];
        __syncthreads();
        long long r = (long long)bid * 256 + tid;
        if (r >= Nn) return;
        float acc[HID];
#pragma unroll
        for (int j = 0; j < HID; j++) acc[j] = 0.f;
        const float4* xr = (const float4*)(x + r * IN_C);
#pragma unroll 4
        for (int k = 0; k < IN_C / 4; k++) {
            float4 v = __ldg(&xr[k]);
            const float* w = &Ws[(k * 4) * HID];
#pragma unroll
            for (int j = 0; j < HID; j++)
                acc[j] += v.x * w[j] + v.y * w[HID + j] + v.z * w[2 * HID + j] + v.w * w[3 * HID + j];
        }
        float4* o = (float4*)&g_h1[r * HID];
#pragma unroll
        for (int q = 0; q < HID / 4; q++)
            o[q] = make_float4(acc[4*q], acc[4*q+1], acc[4*q+2], acc[4*q+3]);
    } else {
        long long e = (long long)(bid - mmBlocks) * 256 + tid;
        if (e >= E) return;
        int c;
        if (g_is32) c = ((const int*)ei)[E + e];
        else        c = (int)((const long long*)ei)[E + e];
        g_rank[e] = atomicAdd(&g_cnt[c], 1);   // rank doubles as the CSR slot
    }
}

// ---------------- single-kernel scan (decoupled lookback) --------------------
__global__ __launch_bounds__(256) void scan_dl_kernel(int n, long long E) {
    __shared__ int wsum[8];
    __shared__ int woff[8];
    __shared__ int s_off;
    int t = threadIdx.x;
    int b = blockIdx.x;
    int base = b * SCHUNK + t * 4;
    int v0 = base + 0 < n ? g_cnt[base + 0] : 0;
    int v1 = base + 1 < n ? g_cnt[base + 1] : 0;
    int v2 = base + 2 < n ? g_cnt[base + 2] : 0;
    int v3 = base + 3 < n ? g_cnt[base + 3] : 0;
    // fused dinv: rsqrt(deg + 1)   (+1 = self loop)
    if (base + 0 < n) g_dinv[base + 0] = rsqrtf((float)v0 + 1.0f);
    if (base + 1 < n) g_dinv[base + 1] = rsqrtf((float)v1 + 1.0f);
    if (base + 2 < n) g_dinv[base + 2] = rsqrtf((float)v2 + 1.0f);
    if (base + 3 < n) g_dinv[base + 3] = rsqrtf((float)v3 + 1.0f);
    int tsum = v0 + v1 + v2 + v3;
    int lane = t & 31, w = t >> 5;
    int x = tsum;
#pragma unroll
    for (int off = 1; off < 32; off <<= 1) {
        int y = __shfl_up_sync(0xffffffff, x, off);
        if (lane >= off) x += y;
    }
    if (lane == 31) wsum[w] = x;
    __syncthreads();
    if (t == 0) {
        int acc = 0;
#pragma unroll
        for (int i = 0; i < 8; i++) { int tmp = wsum[i]; woff[i] = acc; acc += tmp; }
        g_aggval[b] = acc;
        __threadfence();
        ((volatile int*)g_flag)[b] = 1;
    }
    if (t < 32) {
        int sum = 0;
        for (int w0 = 0; w0 < b; w0 += 32) {
            int idx = w0 + lane;
            int a = 0;
            if (idx < b) {
                while (((volatile int*)g_flag)[idx] == 0) {}
                __threadfence();
                a = ((volatile int*)g_aggval)[idx];
            }
#pragma unroll
            for (int off = 16; off >= 1; off >>= 1)
                a += __shfl_xor_sync(0xffffffff, a, off);
            sum += a;
        }
        if (lane == 0) s_off = sum;
    }
    __syncthreads();
    int excl = s_off + woff[w] + (x - tsum);
    if (base + 0 < n) g_rowptr[base + 0] = excl;
    if (base + 1 < n) g_rowptr[base + 1] = excl + v0;
    if (base + 2 < n) g_rowptr[base + 2] = excl + v0 + v1;
    if (base + 3 < n) g_rowptr[base + 3] = excl + v0 + v1 + v2;
    if (base == 0) g_rowptr[n] = (int)E;
}

// ---------------- M2: scale h1 -> fp16 table  ∥  atomic-free CSR fill --------
__global__ __launch_bounds__(256) void m2_kernel(const void* ei, long long E,
                                                 long long Nn, unsigned scaleBlocks) {
    unsigned bid = blockIdx.x;
    int tid = threadIdx.x;
    if (bid < scaleBlocks) {
        long long i = (long long)bid * 256 + tid;       // float4 index (Nn*4 total)
        if (i < Nn * (HID / 4)) {
            float d = g_dinv[i >> 2];
            float4 v = ((const float4*)g_h1)[i];
            __half2 h0 = __floats2half2_rn(v.x * d, v.y * d);
            __half2 h1 = __floats2half2_rn(v.z * d, v.w * d);
            unsigned u0 = *(unsigned*)&h0;
            unsigned u1 = *(unsigned*)&h1;
            ((uint2*)g_h1h)[i] = make_uint2(u0, u1);
        }
    } else {
        long long e = (long long)(bid - scaleBlocks) * 256 + tid;
        if (e >= E) return;
        int r, c;
        if (g_is32) {
            const int* p = (const int*)ei;
            r = p[e]; c = p[E + e];
        } else {
            const long long* p = (const long long*)ei;
            r = (int)p[e]; c = (int)p[E + e];
        }
        int pos = __ldg(&g_rowptr[c]) + g_rank[e];
        g_csrc[pos] = r;
    }
}

// ---------------- layer-1 aggregation: one warp per node (fp16 gathers) ------
// lane = 8*sub + h: sub (0..3) indexes edges, h (0..7) indexes half2 chunks.
__global__ __launch_bounds__(256) void agg1_kernel(const float* __restrict__ b1,
                                                   long long Nn) {
    long long c = ((long long)blockIdx.x * blockDim.x + threadIdx.x) >> 5;
    if (c >= Nn) return;
    int lane = threadIdx.x & 31;
    int h = lane & 7, sub = lane >> 3;
    int beg = g_rowptr[c], end = g_rowptr[c + 1];
    float2 a = make_float2(0.f, 0.f);
    int e = beg + sub;
    for (; e + 4 < end; e += 8) {
        int s0 = __ldg(&g_csrc[e]);
        int s1 = __ldg(&g_csrc[e + 4]);
        float2 f0 = __half22float2(__ldg(&g_h1h[(long long)s0 * 8 + h]));
        float2 f1 = __half22float2(__ldg(&g_h1h[(long long)s1 * 8 + h]));
        a.x += f0.x + f1.x;
        a.y += f0.y + f1.y;
    }
    if (e < end) {
        int s0 = __ldg(&g_csrc[e]);
        float2 f0 = __half22float2(__ldg(&g_h1h[(long long)s0 * 8 + h]));
        a.x += f0.x; a.y += f0.y;
    }
    // butterfly over sub (lane bits 3,4)
#pragma unroll
    for (int off = 16; off >= 8; off >>= 1) {
        a.x += __shfl_xor_sync(0xffffffff, a.x, off);
        a.y += __shfl_xor_sync(0xffffffff, a.y, off);
    }
    if (sub == 0) {
        float d = g_dinv[c];
        float2 self = __half22float2(__ldg(&g_h1h[c * 8 + h]));
        float2 b = ((const float2*)b1)[h];
        float zx = fmaxf(d * (a.x + self.x) + b.x, 0.f) * d;
        float zy = fmaxf(d * (a.y + self.y) + b.y, 0.f) * d;
        g_zsh[c * 8 + h] = __floats2half2_rn(zx, zy);
    }
}

// ---------------- layer-2 aggregation + fused GEMM + bias (fp16 gathers) -----
__global__ __launch_bounds__(256) void agg2mm_kernel(const float* __restrict__ W2,
                                                     const float* __restrict__ b2,
                                                     float* __restrict__ out,
                                                     long long Nn) {
    __shared__ float Ws[HID * OUTC];   // 4 KB
    for (int i = threadIdx.x; i < HID * OUTC; i += 256) Ws[i] = W2[i];
    __syncthreads();

    long long c = ((long long)blockIdx.x * blockDim.x + threadIdx.x) >> 5;
    if (c >= Nn) return;
    int lane = threadIdx.x & 31;
    int h = lane & 7, sub = lane >> 3;
    int beg = g_rowptr[c], end = g_rowptr[c + 1];
    float2 a = make_float2(0.f, 0.f);
    int e = beg + sub;
    for (; e + 4 < end; e += 8) {
        int s0 = __ldg(&g_csrc[e]);
        int s1 = __ldg(&g_csrc[e + 4]);
        float2 f0 = __half22float2(__ldg(&g_zsh[(long long)s0 * 8 + h]));
        float2 f1 = __half22float2(__ldg(&g_zsh[(long long)s1 * 8 + h]));
        a.x += f0.x + f1.x;
        a.y += f0.y + f1.y;
    }
    if (e < end) {
        int s0 = __ldg(&g_csrc[e]);
        float2 f0 = __half22float2(__ldg(&g_zsh[(long long)s0 * 8 + h]));
        a.x += f0.x; a.y += f0.y;
    }
#pragma unroll
    for (int off = 16; off >= 8; off >>= 1) {
        a.x += __shfl_xor_sync(0xffffffff, a.x, off);
        a.y += __shfl_xor_sync(0xffffffff, a.y, off);
    }
    // every lane now holds the total for its h-chunk; fold in self + dinv
    float d = g_dinv[c];
    float2 self = __half22float2(__ldg(&g_zsh[c * 8 + h]));
    float2 vq;
    vq.x = d * (a.x + self.x);
    vq.y = d * (a.y + self.y);

    // broadcast v[16]: component k lives in lane (k>>1), field (k&1)
    float vv[HID];
#pragma unroll
    for (int k = 0; k < HID; k++)
        vv[k] = __shfl_sync(0xffffffff, (k & 1) ? vq.y : vq.x, k >> 1);

    // lane computes output columns 2*lane, 2*lane+1
    float2 o = ((const float2*)b2)[lane];
#pragma unroll
    for (int k = 0; k < HID; k++) {
        float xv = vv[k];
        float2 w = ((const float2*)Ws)[k * (OUTC / 2) + lane];
        o.x += xv * w.x;
        o.y += xv * w.y;
    }
    ((float2*)(out + c * OUTC))[lane] = o;
}

// ---------------- launch ----------------------------------------------------
extern "C" void kernel_launch(void* const* d_in, const int* in_sizes, int n_in,
                              void* d_out, int out_size) {
    const float* x  = (const float*)d_in[0];
    const void*  ei = d_in[1];
    const float* W1 = (const float*)d_in[2];
    const float* b1 = (const float*)d_in[3];
    const float* W2 = (const float*)d_in[4];
    const float* b2 = (const float*)d_in[5];
    float* out = (float*)d_out;

    long long Nn = in_sizes[0] / IN_C;
    long long E  = (long long)in_sizes[1] / 2;

    const int T = 256;
    unsigned zBlocks  = (unsigned)((Nn + T - 1) / T);
    unsigned mmBlocks = (unsigned)((Nn + T - 1) / T);
    unsigned edBlocks = (unsigned)((E + T - 1) / T);
    unsigned scBlocks = (unsigned)((Nn * (HID/4) + T - 1) / T);
    unsigned gW = (unsigned)((Nn * 32 + T - 1) / T);
    int nb = (int)((Nn + SCHUNK - 1) / SCHUNK);

    setup_kernel  <<<zBlocks + 1, T>>>(ei, E, Nn, zBlocks);
    m1_kernel     <<<mmBlocks + edBlocks, T>>>(x, W1, ei, Nn, E, mmBlocks);
    scan_dl_kernel<<<nb, T>>>((int)Nn, E);
    m2_kernel     <<<scBlocks + edBlocks, T>>>(ei, E, Nn, scBlocks);
    agg1_kernel   <<<gW, T>>>(b1, Nn);
    agg2mm_kernel <<<gW, T>>>(W2, b2, out, Nn);
}